// round 4
// baseline (speedup 1.0000x reference)
#include <cuda_runtime.h>
#include <math.h>

// Problem constants
#define SEG      32
#define DD       256          // embedding dim D
#define ROWS     32768        // B*N
#define DIM      257          // Lorentz dim D+1
#define TILE     8            // rows per block tile
#define TILES    (ROWS / TILE)   // 4096

// ---------------- packed f32x2 helpers ----------------
typedef struct __align__(16) { unsigned long long a, b; } u64x2;

__device__ __forceinline__ unsigned long long pack2(float lo, float hi) {
    unsigned long long r;
    asm("mov.b64 %0, {%1, %2};" : "=l"(r) : "f"(lo), "f"(hi));
    return r;
}
__device__ __forceinline__ void unpack2(unsigned long long v, float& lo, float& hi) {
    asm("mov.b64 {%0, %1}, %2;" : "=f"(lo), "=f"(hi) : "l"(v));
}
__device__ __forceinline__ void ffma2(unsigned long long& d,
                                      unsigned long long a, unsigned long long b) {
    asm("fma.rn.f32x2 %0, %1, %2, %0;" : "+l"(d) : "l"(a), "l"(b));
}

__device__ __forceinline__ float wredsum(float v) {
    v += __shfl_xor_sync(0xffffffffu, v, 16);
    v += __shfl_xor_sync(0xffffffffu, v, 8);
    v += __shfl_xor_sync(0xffffffffu, v, 4);
    v += __shfl_xor_sync(0xffffffffu, v, 2);
    v += __shfl_xor_sync(0xffffffffu, v, 1);
    return v;
}

// One fused kernel. Block = 1024 threads, thread = (series s = tid>>8, dim d = tid&255).
// Per tile (8 rows): encode -> zsm; 8 gram-warps compute z-Gram + full scalar
// Karcher chain (redundant per lane, no divergence); 32 warps write h and combined.
__global__ __launch_bounds__(1024, 1)
void splm_one_kernel(const float* __restrict__ xt, const float* __restrict__ xc,
                     const float* __restrict__ xf, const float* __restrict__ xr,
                     const float* __restrict__ W0, const float* __restrict__ b0,
                     const float* __restrict__ W1, const float* __restrict__ b1,
                     const float* __restrict__ W2, const float* __restrict__ b2,
                     const float* __restrict__ W3, const float* __restrict__ b3,
                     const float* __restrict__ esp, const float* __restrict__ lwp,
                     float* __restrict__ out)
{
    __shared__ float xs[1024];              // [s][row][k] = s*256 + row*32 + k
    __shared__ float zsm[TILE * 4 * DD];    // [(row*4+s)*256 + d]  (32 KB)
    __shared__ float gsm[TILE * 16];        // per row: F[4], tP[4], gamF[4], tm

    const int tid = threadIdx.x;
    const int w = tid >> 5;
    const int l = tid & 31;
    const int s = tid >> 8;
    const int d = tid & 255;

    const float* Wp = (s == 0) ? W0 : (s == 1) ? W1 : (s == 2) ? W2 : W3;
    const float* bp = (s == 0) ? b0 : (s == 1) ? b1 : (s == 2) ? b2 : b3;
    const float* xp = (s == 0) ? xt : (s == 1) ? xc : (s == 2) ? xf : xr;

    // W row for (s, d): 32 floats -> 16 packed f32x2 over K pairs
    unsigned long long wp[16];
    {
        const u64x2* W16 = (const u64x2*)(Wp + d * SEG);
        #pragma unroll
        for (int i = 0; i < 8; i++) {
            u64x2 v = W16[i];
            wp[2 * i]     = v.a;
            wp[2 * i + 1] = v.b;
        }
    }
    const float bias = bp[d];

    const float ta  = tanhf(*esp);
    const float taa = fabsf(ta);

    // softmax weights
    float lw0 = lwp[0], lw1 = lwp[1], lw2 = lwp[2], lw3 = lwp[3];
    float mxw = fmaxf(fmaxf(lw0, lw1), fmaxf(lw2, lw3));
    float e0 = expf(lw0 - mxw), e1 = expf(lw1 - mxw);
    float e2 = expf(lw2 - mxw), e3 = expf(lw3 - mxw);
    float esum = e0 + e1 + e2 + e3;
    float wgt[4] = {e0 / esum, e1 / esum, e2 / esum, e3 / esum};

    int tile = blockIdx.x;
    float v = xp[tile * 256 + d + (s - s) ];   // prefetch (index = tile*256 + (tid&255))
    v = xp[tile * 256 + d];

    for (; tile < TILES; tile += gridDim.x) {
        __syncthreads();                 // xs/zsm free (prev write phase done)
        xs[s * 256 + d] = v;             // = xs[tid]
        __syncthreads();

        int nt = tile + gridDim.x;
        if (nt < TILES) v = xp[nt * 256 + d];   // prefetch overlaps compute

        // ---- encode: 8 rows, packed FMA ----
        unsigned long long acc[TILE];
        #pragma unroll
        for (int r = 0; r < TILE; r++) acc[r] = pack2(bias, 0.f);

        #pragma unroll
        for (int r = 0; r < TILE; r++) {
            const u64x2* x16 = (const u64x2*)(xs + s * 256 + r * SEG);
            #pragma unroll
            for (int i = 0; i < 8; i++) {
                u64x2 xv = x16[i];       // LDS.128 broadcast
                ffma2(acc[r], wp[2 * i],     xv.a);
                ffma2(acc[r], wp[2 * i + 1], xv.b);
            }
        }
        #pragma unroll
        for (int r = 0; r < TILE; r++) {
            float lo, hi;
            unpack2(acc[r], lo, hi);
            zsm[(r * 4 + s) * DD + d] = lo + hi;
        }
        __syncthreads();

        // ---- gram + scalar chain: warps 0..7, warp = row ----
        if (w < 8) {
            const int row = w;

            // z-Gram (economical register use: reload zb per pair)
            float Zg[4][4];
            float za[8], zb[8];
            #pragma unroll
            for (int c = 0; c < 4; c++) {
                #pragma unroll
                for (int j = 0; j < 8; j++) za[j] = zsm[(row * 4 + c) * DD + l + 32 * j];
                float lo = 0.f;
                #pragma unroll
                for (int j = 0; j < 8; j++) lo = fmaf(za[j], za[j], lo);
                Zg[c][c] = lo;
                #pragma unroll
                for (int dd2 = 0; dd2 < 4; dd2++) {
                    if (dd2 > c) {
                        #pragma unroll
                        for (int j = 0; j < 8; j++) zb[j] = zsm[(row * 4 + dd2) * DD + l + 32 * j];
                        float lo2 = 0.f;
                        #pragma unroll
                        for (int j = 0; j < 8; j++) lo2 = fmaf(za[j], zb[j], lo2);
                        Zg[c][dd2] = lo2;
                    }
                }
            }
            #pragma unroll
            for (int c = 0; c < 4; c++)
                #pragma unroll
                for (int dd2 = 0; dd2 < 4; dd2++)
                    if (dd2 > c) Zg[c][dd2] = wredsum(Zg[c][dd2]);
            #pragma unroll
            for (int c = 0; c < 4; c++) Zg[c][c] = wredsum(Zg[c][c]);
            #pragma unroll
            for (int c = 0; c < 4; c++)
                #pragma unroll
                for (int dd2 = 0; dd2 < c; dd2++) Zg[c][dd2] = Zg[dd2][c];

            // hyperbolic scalars per series (all lanes redundant)
            float F[4], tP[4];
            #pragma unroll
            for (int c = 0; c < 4; c++) {
                float zn = sqrtf(Zg[c][c]);
                float n  = taa * zn;
                float s1 = ta * fminf(n, 1.5f) / fmaxf(n, 1e-8f);
                float nn = fabsf(s1) * zn;
                float ns = fmaxf(nn, 1e-9f);
                float sh = sinhf(nn);
                F[c]  = s1 * sh / ns;
                float sx = sh * nn / ns;
                tP[c] = sqrtf(1.f + sx * sx);
            }

            // h-space Gram: P = F_c F_d Zg
            float P[4][4], S[4];
            #pragma unroll
            for (int c = 0; c < 4; c++)
                #pragma unroll
                for (int dd2 = 0; dd2 < 4; dd2++)
                    P[c][dd2] = F[c] * F[dd2] * Zg[c][dd2];
            #pragma unroll
            for (int c = 0; c < 4; c++) S[c] = P[c][c];

            // init: logmap(origin), clip, expmap0+projx
            float gam[4];
            float wt_t = 0.f;
            #pragma unroll
            for (int c = 0; c < 4; c++) {
                float alpha = fmaxf(tP[c], 1.0f + 1e-7f);
                float dist  = acoshf(alpha);
                float ut    = tP[c] - alpha;
                float un2   = fmaxf(S[c] - ut * ut, 1e-12f);
                float g     = dist / sqrtf(un2);
                float wg    = wgt[c] * g;
                gam[c] = wg;
                wt_t   = fmaf(wg, ut, wt_t);
            }
            float wtsp2;
            {
                float t = 0.f;
                #pragma unroll
                for (int c = 0; c < 4; c++) {
                    float u = 0.f;
                    #pragma unroll
                    for (int dd2 = 0; dd2 < 4; dd2++) u = fmaf(gam[dd2], P[c][dd2], u);
                    t = fmaf(gam[c], u, t);
                }
                wtsp2 = fmaxf(t, 0.f);
            }
            float Ssm, tm;
            {
                float nrm = sqrtf(wtsp2 + wt_t * wt_t);
                float cs  = fminf(nrm, 2.0f) / fmaxf(nrm, 1e-12f);
                float S2  = cs * cs * wtsp2;
                float nn  = sqrtf(S2);
                float ns  = fmaxf(nn, 1e-9f);
                float sh  = sinhf(nn);
                float fac = cs * sh / ns;
                #pragma unroll
                for (int c = 0; c < 4; c++) gam[c] *= fac;
                float sx = sh * nn / ns;
                Ssm = sx * sx;
                tm  = sqrtf(1.f + Ssm);
            }

            // 5 Karcher iterations (scalar)
            #pragma unroll
            for (int it = 0; it < 5; it++) {
                float dl[4];
                #pragma unroll
                for (int c = 0; c < 4; c++) {
                    float t = 0.f;
                    #pragma unroll
                    for (int dd2 = 0; dd2 < 4; dd2++) t = fmaf(gam[dd2], P[dd2][c], t);
                    dl[c] = t;
                }
                float wgv[4], utv[4];
                float A = 0.f, wv_t = 0.f;
                #pragma unroll
                for (int c = 0; c < 4; c++) {
                    float alpha = fmaxf(tm * tP[c] - dl[c], 1.0f + 1e-7f);
                    float dist  = acoshf(alpha);
                    float ut    = tP[c] - alpha * tm;
                    float U2sp  = S[c] - 2.f * alpha * dl[c] + alpha * alpha * Ssm;
                    float un2   = fmaxf(U2sp - ut * ut, 1e-12f);
                    float g     = dist / sqrtf(un2);
                    float wg    = wgt[c] * g;
                    wgv[c] = wg; utv[c] = ut;
                    A    = fmaf(wg, alpha, A);
                    wv_t = fmaf(wg, ut, wv_t);
                }
                float wvg[4];
                #pragma unroll
                for (int c = 0; c < 4; c++) wvg[c] = wgv[c] - A * gam[c];

                float wvsp2;
                {
                    float t = 0.f;
                    #pragma unroll
                    for (int c = 0; c < 4; c++) {
                        float u = 0.f;
                        #pragma unroll
                        for (int dd2 = 0; dd2 < 4; dd2++) u = fmaf(wvg[dd2], P[c][dd2], u);
                        t = fmaf(wvg[c], u, t);
                    }
                    wvsp2 = fmaxf(t, 0.f);
                }

                float nrm = sqrtf(wvsp2 + wv_t * wv_t);
                float cs  = fminf(nrm, 2.0f) / fmaxf(nrm, 1e-12f);
                float q   = 0.1f * cs;
                float mk  = fmaxf(q * q * (wvsp2 - wv_t * wv_t), 1e-12f);
                float th  = sqrtf(mk);
                float ch  = coshf(th);
                float shh = sinhf(th);
                float cq  = shh * q / th;

                #pragma unroll
                for (int c = 0; c < 4; c++) gam[c] = fmaf(cq, wvg[c], ch * gam[c]);

                {
                    float t = 0.f;
                    #pragma unroll
                    for (int c = 0; c < 4; c++) {
                        float u = 0.f;
                        #pragma unroll
                        for (int dd2 = 0; dd2 < 4; dd2++) u = fmaf(gam[dd2], P[c][dd2], u);
                        t = fmaf(gam[c], u, t);
                    }
                    Ssm = fmaxf(t, 0.f);
                }
                tm = sqrtf(1.f + Ssm);
            }

            if (l == 0) {
                #pragma unroll
                for (int c = 0; c < 4; c++) {
                    gsm[row * 16 + c]     = F[c];
                    gsm[row * 16 + 4 + c] = tP[c];
                    gsm[row * 16 + 8 + c] = gam[c] * F[c];   // coeff in z-basis
                }
                gsm[row * 16 + 12] = tm;
            }
        }
        __syncthreads();

        // ---- write phase: warp unit (row = w>>2, q = w&3) ----
        {
            const int row = w >> 2;
            const int q   = w & 3;
            const int r   = tile * TILE + row;

            // h for series q
            float Fv  = gsm[row * 16 + q];
            float tPv = gsm[row * 16 + 4 + q];
            float* hp = out + (size_t)q * ((size_t)ROWS * DIM) + (size_t)r * DIM;
            #pragma unroll
            for (int j = 0; j < 8; j++)
                hp[1 + l + 32 * j] = Fv * zsm[(row * 4 + q) * DD + l + 32 * j];
            if (l == 0) hp[0] = tPv;

            // combined: this warp covers dims q*64 .. q*64+63
            float g0 = gsm[row * 16 + 8 + 0];
            float g1 = gsm[row * 16 + 8 + 1];
            float g2 = gsm[row * 16 + 8 + 2];
            float g3 = gsm[row * 16 + 8 + 3];
            float tm = gsm[row * 16 + 12];
            float* cp = out + 4 * ((size_t)ROWS * DIM) + (size_t)r * DIM;
            #pragma unroll
            for (int jj = 0; jj < 2; jj++) {
                int ddim = q * 64 + l + 32 * jj;
                float val = g0 * zsm[(row * 4 + 0) * DD + ddim];
                val = fmaf(g1, zsm[(row * 4 + 1) * DD + ddim], val);
                val = fmaf(g2, zsm[(row * 4 + 2) * DD + ddim], val);
                val = fmaf(g3, zsm[(row * 4 + 3) * DD + ddim], val);
                cp[1 + ddim] = val;
            }
            if (q == 0 && l == 0) cp[0] = tm;
        }
    }
}

extern "C" void kernel_launch(void* const* d_in, const int* in_sizes, int n_in,
                              void* d_out, int out_size) {
    (void)in_sizes; (void)n_in; (void)out_size;
    const float* xt = (const float*)d_in[0];
    const float* xc = (const float*)d_in[1];
    const float* xf = (const float*)d_in[2];
    const float* xr = (const float*)d_in[3];
    const float* W0 = (const float*)d_in[4];
    const float* b0 = (const float*)d_in[5];
    const float* W1 = (const float*)d_in[6];
    const float* b1 = (const float*)d_in[7];
    const float* W2 = (const float*)d_in[8];
    const float* b2 = (const float*)d_in[9];
    const float* W3 = (const float*)d_in[10];
    const float* b3 = (const float*)d_in[11];
    const float* es = (const float*)d_in[12];
    const float* lw = (const float*)d_in[13];
    float* out = (float*)d_out;

    int nsm = 148;
    cudaDeviceGetAttribute(&nsm, cudaDevAttrMultiProcessorCount, 0);
    if (nsm <= 0) nsm = 148;

    splm_one_kernel<<<nsm, 1024>>>(xt, xc, xf, xr,
                                   W0, b0, W1, b1, W2, b2, W3, b3,
                                   es, lw, out);
}

// round 6
// speedup vs baseline: 1.4491x; 1.4491x over previous
#include <cuda_runtime.h>
#include <math.h>

// Problem constants
#define SEG      32
#define DD       256          // embedding dim D
#define ROWS     32768        // B*N
#define DIM      257          // Lorentz dim D+1
#define TILE     8            // rows per tile (per series-block)
#define TILES    (ROWS / TILE)   // 4096 tiles per series

__device__ __forceinline__ float wredsum(float v) {
    v += __shfl_xor_sync(0xffffffffu, v, 16);
    v += __shfl_xor_sync(0xffffffffu, v, 8);
    v += __shfl_xor_sync(0xffffffffu, v, 4);
    v += __shfl_xor_sync(0xffffffffu, v, 2);
    v += __shfl_xor_sync(0xffffffffu, v, 1);
    return v;
}

// ---------------- Kernel 1: encode + hyperbolic ----------------
// Series-per-block (s = blockIdx&3). Thread owns dim d = tid, W row in 8
// float4 regs. 8 rows per tile; k-chunk-outer / row-inner FMA loop gives 8
// interleaved accumulator chains. Warp-per-row hyperbolic epilogue writes h.
__global__ __launch_bounds__(256, 3)
void encode_hyp_kernel(const float* __restrict__ xt, const float* __restrict__ xc,
                       const float* __restrict__ xf, const float* __restrict__ xr,
                       const float* __restrict__ W0, const float* __restrict__ b0,
                       const float* __restrict__ W1, const float* __restrict__ b1,
                       const float* __restrict__ W2, const float* __restrict__ b2,
                       const float* __restrict__ W3, const float* __restrict__ b3,
                       const float* __restrict__ esp,
                       float* __restrict__ out)
{
    __shared__ float xs[TILE * SEG];     // 256 floats
    __shared__ float zsm[TILE * DD];     // 8 KB

    const int tid = threadIdx.x;
    const int w = tid >> 5;
    const int l = tid & 31;

    const int s      = blockIdx.x & 3;
    const int chunk  = blockIdx.x >> 2;
    const int stride = gridDim.x >> 2;

    const float* Wp = (s == 0) ? W0 : (s == 1) ? W1 : (s == 2) ? W2 : W3;
    const float* bp = (s == 0) ? b0 : (s == 1) ? b1 : (s == 2) ? b2 : b3;
    const float* xp = (s == 0) ? xt : (s == 1) ? xc : (s == 2) ? xf : xr;

    float4 Wreg[8];
    {
        const float4* W4 = (const float4*)(Wp + tid * SEG);
        #pragma unroll
        for (int i = 0; i < 8; i++) Wreg[i] = W4[i];
    }
    const float bias = bp[tid];

    const float ta  = tanhf(*esp);
    const float taa = fabsf(ta);

    int tile = chunk;
    float v = (tile < TILES) ? xp[tile * (TILE * SEG) + tid] : 0.f;

    for (; tile < TILES; tile += stride) {
        __syncthreads();
        xs[tid] = v;                        // tile is 256 floats = blockDim
        __syncthreads();

        int nt = tile + stride;
        if (nt < TILES) v = xp[nt * (TILE * SEG) + tid];   // prefetch

        // encode: 8 interleaved accumulator chains
        float acc[TILE];
        #pragma unroll
        for (int r = 0; r < TILE; r++) acc[r] = bias;

        #pragma unroll
        for (int i = 0; i < 8; i++) {
            const float4 wv = Wreg[i];
            #pragma unroll
            for (int r = 0; r < TILE; r++) {
                float4 xv = *(const float4*)(xs + r * SEG + i * 4);
                float a = acc[r];
                a = fmaf(wv.x, xv.x, a);
                a = fmaf(wv.y, xv.y, a);
                a = fmaf(wv.z, xv.z, a);
                a = fmaf(wv.w, xv.w, a);
                acc[r] = a;
            }
        }

        #pragma unroll
        for (int r = 0; r < TILE; r++) zsm[r * DD + tid] = acc[r];
        __syncthreads();

        // hyperbolic: warp w -> row w
        {
            const int r = tile * TILE + w;

            float z[8];
            float lo = 0.f;
            #pragma unroll
            for (int j = 0; j < 8; j++) {
                z[j] = zsm[w * DD + l + 32 * j];
                lo = fmaf(z[j], z[j], lo);
            }
            lo = wredsum(lo);

            float zn = sqrtf(lo);
            float n  = taa * zn;
            float s1 = ta * fminf(n, 1.5f) / fmaxf(n, 1e-8f);
            float nn = fabsf(s1) * zn;           // ||v_clipped||
            float ns = fmaxf(nn, 1e-9f);
            float sh = sinhf(nn);
            float F  = s1 * sh / ns;             // xr = F * z
            float sx = sh * nn / ns;             // ||xr||
            float x0v = sqrtf(1.f + sx * sx);    // projx time

            float* hp = out + (size_t)s * ((size_t)ROWS * DIM) + (size_t)r * DIM;
            #pragma unroll
            for (int j = 0; j < 8; j++) hp[1 + l + 32 * j] = z[j] * F;
            if (l == 0) hp[0] = x0v;
        }
    }
}

// ---------------- Kernel 2: fusion, barrier-free warp-per-row ----------------
// Each warp owns one row: loads the 4 points, Gram via warp reductions, runs
// the scalar Karcher chain replicated in all lanes (same warp-instr count as
// lane-packed, but no cross-warp serialization), writes combined with __stcs.
__global__ __launch_bounds__(256, 3)
void fusion_kernel(const float* __restrict__ lwp, float* __restrict__ out)
{
    const int w = threadIdx.x >> 5;
    const int l = threadIdx.x & 31;
    // reverse row order: read what K1 wrote most recently (L2-hot)
    const int r = (ROWS - 8) - blockIdx.x * 8 + w;

    // softmax weights
    float lw0 = lwp[0], lw1 = lwp[1], lw2 = lwp[2], lw3 = lwp[3];
    float mxw = fmaxf(fmaxf(lw0, lw1), fmaxf(lw2, lw3));
    float e0 = expf(lw0 - mxw), e1 = expf(lw1 - mxw);
    float e2 = expf(lw2 - mxw), e3 = expf(lw3 - mxw);
    float esum = e0 + e1 + e2 + e3;
    float wgt[4] = {e0 / esum, e1 / esum, e2 / esum, e3 / esum};

    // load 4 hyperbolic points
    float sP[4][8], tP[4];
    #pragma unroll
    for (int c = 0; c < 4; c++) {
        const float* hp = out + (size_t)c * ((size_t)ROWS * DIM) + (size_t)r * DIM;
        tP[c] = __ldg(hp);
        #pragma unroll
        for (int j = 0; j < 8; j++) sP[c][j] = __ldg(hp + 1 + l + 32 * j);
    }

    // Gram (10 unique entries)
    float pr[10];
    {
        int idx = 0;
        #pragma unroll
        for (int c = 0; c < 4; c++)
            #pragma unroll
            for (int d = c; d < 4; d++) {
                float lo = 0.f;
                #pragma unroll
                for (int j = 0; j < 8; j++) lo = fmaf(sP[c][j], sP[d][j], lo);
                pr[idx++] = lo;
            }
    }
    #pragma unroll
    for (int i = 0; i < 10; i++) pr[i] = wredsum(pr[i]);

    float P[4][4];
    {
        int idx = 0;
        #pragma unroll
        for (int c = 0; c < 4; c++)
            #pragma unroll
            for (int d = c; d < 4; d++) {
                P[c][d] = pr[idx]; P[d][c] = pr[idx]; idx++;
            }
    }
    float S[4];
    #pragma unroll
    for (int c = 0; c < 4; c++) S[c] = P[c][c];

    // init: logmap(origin), clip, expmap0 + projx
    float gam[4];
    float wt_t = 0.f;
    #pragma unroll
    for (int c = 0; c < 4; c++) {
        float alpha = fmaxf(tP[c], 1.0f + 1e-7f);
        float dist  = acoshf(alpha);
        float ut    = tP[c] - alpha;
        float un2   = fmaxf(S[c] - ut * ut, 1e-12f);
        float g     = dist / sqrtf(un2);
        float wg    = wgt[c] * g;
        gam[c] = wg;
        wt_t   = fmaf(wg, ut, wt_t);
    }
    float wtsp2;
    {
        float t = 0.f;
        #pragma unroll
        for (int c = 0; c < 4; c++) {
            float u = 0.f;
            #pragma unroll
            for (int d = 0; d < 4; d++) u = fmaf(gam[d], P[c][d], u);
            t = fmaf(gam[c], u, t);
        }
        wtsp2 = fmaxf(t, 0.f);
    }
    float Ssm, tm;
    {
        float nrm = sqrtf(wtsp2 + wt_t * wt_t);
        float cs  = fminf(nrm, 2.0f) / fmaxf(nrm, 1e-12f);
        float S2  = cs * cs * wtsp2;
        float nn  = sqrtf(S2);
        float ns  = fmaxf(nn, 1e-9f);
        float sh  = sinhf(nn);
        float fac = cs * sh / ns;
        #pragma unroll
        for (int c = 0; c < 4; c++) gam[c] *= fac;
        float sx = sh * nn / ns;
        Ssm = sx * sx;
        tm  = sqrtf(1.f + Ssm);
    }

    // 5 Karcher iterations (scalar, lane-replicated)
    #pragma unroll
    for (int it = 0; it < 5; it++) {
        float dl[4];
        #pragma unroll
        for (int c = 0; c < 4; c++) {
            float t = 0.f;
            #pragma unroll
            for (int d = 0; d < 4; d++) t = fmaf(gam[d], P[d][c], t);
            dl[c] = t;
        }
        float wgv[4], utv[4];
        float A = 0.f, wv_t = 0.f;
        #pragma unroll
        for (int c = 0; c < 4; c++) {
            float alpha = fmaxf(tm * tP[c] - dl[c], 1.0f + 1e-7f);
            float dist  = acoshf(alpha);
            float ut    = tP[c] - alpha * tm;
            float U2sp  = S[c] - 2.f * alpha * dl[c] + alpha * alpha * Ssm;
            float un2   = fmaxf(U2sp - ut * ut, 1e-12f);
            float g     = dist / sqrtf(un2);
            float wg    = wgt[c] * g;
            wgv[c] = wg; utv[c] = ut;
            A    = fmaf(wg, alpha, A);
            wv_t = fmaf(wg, ut, wv_t);
        }
        float wvg[4];
        #pragma unroll
        for (int c = 0; c < 4; c++) wvg[c] = wgv[c] - A * gam[c];

        float wvsp2;
        {
            float t = 0.f;
            #pragma unroll
            for (int c = 0; c < 4; c++) {
                float u = 0.f;
                #pragma unroll
                for (int d = 0; d < 4; d++) u = fmaf(wvg[d], P[c][d], u);
                t = fmaf(wvg[c], u, t);
            }
            wvsp2 = fmaxf(t, 0.f);
        }

        float nrm = sqrtf(wvsp2 + wv_t * wv_t);
        float cs  = fminf(nrm, 2.0f) / fmaxf(nrm, 1e-12f);
        float q   = 0.1f * cs;
        float mk  = fmaxf(q * q * (wvsp2 - wv_t * wv_t), 1e-12f);
        float th  = sqrtf(mk);
        float ch  = coshf(th);
        float shh = sinhf(th);
        float cq  = shh * q / th;

        #pragma unroll
        for (int c = 0; c < 4; c++) gam[c] = fmaf(cq, wvg[c], ch * gam[c]);

        {
            float t = 0.f;
            #pragma unroll
            for (int c = 0; c < 4; c++) {
                float u = 0.f;
                #pragma unroll
                for (int d = 0; d < 4; d++) u = fmaf(gam[d], P[c][d], u);
                t = fmaf(gam[c], u, t);
            }
            Ssm = fmaxf(t, 0.f);
        }
        tm = sqrtf(1.f + Ssm);
    }

    // write combined (streaming stores; never re-read)
    float* cp = out + 4 * ((size_t)ROWS * DIM) + (size_t)r * DIM;
    #pragma unroll
    for (int j = 0; j < 8; j++) {
        float vv = gam[0] * sP[0][j];
        vv = fmaf(gam[1], sP[1][j], vv);
        vv = fmaf(gam[2], sP[2][j], vv);
        vv = fmaf(gam[3], sP[3][j], vv);
        __stcs(cp + 1 + l + 32 * j, vv);
    }
    if (l == 0) __stcs(cp, tm);
}

extern "C" void kernel_launch(void* const* d_in, const int* in_sizes, int n_in,
                              void* d_out, int out_size) {
    (void)in_sizes; (void)n_in; (void)out_size;
    const float* xt = (const float*)d_in[0];
    const float* xc = (const float*)d_in[1];
    const float* xf = (const float*)d_in[2];
    const float* xr = (const float*)d_in[3];
    const float* W0 = (const float*)d_in[4];
    const float* b0 = (const float*)d_in[5];
    const float* W1 = (const float*)d_in[6];
    const float* b1 = (const float*)d_in[7];
    const float* W2 = (const float*)d_in[8];
    const float* b2 = (const float*)d_in[9];
    const float* W3 = (const float*)d_in[10];
    const float* b3 = (const float*)d_in[11];
    const float* es = (const float*)d_in[12];
    const float* lw = (const float*)d_in[13];
    float* out = (float*)d_out;

    int nsm = 148;
    cudaDeviceGetAttribute(&nsm, cudaDevAttrMultiProcessorCount, 0);
    if (nsm <= 0) nsm = 148;

    encode_hyp_kernel<<<12 * nsm, 256>>>(xt, xc, xf, xr,
                                         W0, b0, W1, b1, W2, b2, W3, b3,
                                         es, out);
    fusion_kernel<<<ROWS / 8, 256>>>(lw, out);
}